// round 3
// baseline (speedup 1.0000x reference)
#include <cuda_runtime.h>
#include <cuda_bf16.h>
#include <math.h>

#define BATCH   128
#define OUT_DIM 1024
#define IN_DIM  2048
#define MAXNNZ  64          // Poisson(8): P(row nnz > 64) ~ 1e-40 — safe cap
#define NSTRAIGHT 16        // straight-line gather count (P(n>16) ~ 0.18%/lane)

// Scratch (no allocations allowed): transposed index table, sentinel-padded.
// g_idxT[j][o] = column of j-th nonzero of mask row o (unordered), or IN_DIM
// (sentinel -> multiplies by 1.0f) for j in [n, NSTRAIGHT).
__device__ int            g_cnt[OUT_DIM];
__device__ unsigned short g_idxT[MAXNNZ][OUT_DIM];

// ---------------------------------------------------------------------------
// Kernel 1: one warp per mask row. Entire 8KB row in flight as 16 independent
// float4 loads per lane (one memory epoch). Compaction = per-lane nonzero
// count + one warp shfl-scan + per-lane scatter (order-free: the downstream
// product is commutative and we have 4 decades of rel_err headroom).
// ---------------------------------------------------------------------------
__global__ void __launch_bounds__(128)
build_row_indices(const float* __restrict__ mask) {
    int warp = (blockIdx.x * blockDim.x + threadIdx.x) >> 5;
    int lane = threadIdx.x & 31;
    if (warp >= OUT_DIM) return;

    const float4* row4 =
        reinterpret_cast<const float4*>(mask + (size_t)warp * IN_DIM);

    float4 v[16];                       // whole row: 16 x 32 lanes x 16B = 8KB
    #pragma unroll
    for (int u = 0; u < 16; u++)
        v[u] = row4[u * 32 + lane];     // all independent -> full MLP

    int mycnt = 0;
    #pragma unroll
    for (int u = 0; u < 16; u++)
        mycnt += (v[u].x != 0.0f) + (v[u].y != 0.0f) +
                 (v[u].z != 0.0f) + (v[u].w != 0.0f);

    // inclusive warp scan -> exclusive offset
    int scan = mycnt;
    #pragma unroll
    for (int d = 1; d < 32; d <<= 1) {
        int t = __shfl_up_sync(0xffffffffu, scan, d);
        if (lane >= d) scan += t;
    }
    int total = __shfl_sync(0xffffffffu, scan, 31);
    int pos   = scan - mycnt;           // exclusive prefix

    #pragma unroll
    for (int u = 0; u < 16; u++) {
        float m[4] = {v[u].x, v[u].y, v[u].z, v[u].w};
        #pragma unroll
        for (int k = 0; k < 4; k++) {
            if (m[k] != 0.0f) {
                if (pos < MAXNNZ)
                    g_idxT[pos][warp] =
                        (unsigned short)((u * 32 + lane) * 4 + k);
                pos++;
            }
        }
    }
    // sentinel-pad [total, NSTRAIGHT)
    for (int j = total + lane; j < NSTRAIGHT; j += 32)
        g_idxT[j][warp] = (unsigned short)IN_DIM;

    if (lane == 0) g_cnt[warp] = total < MAXNNZ ? total : MAXNNZ;
}

// ---------------------------------------------------------------------------
// Kernel 2: block = one batch b x 512 consecutive check nodes.
// Straight-line: stage x row to shared (+1.0f sentinel slot), 16 coalesced
// index loads all in flight before the barrier, 16 unconditional LDS gathers,
// product tree, 2*atanh. Exact-bound tail loop only for the ~6% of warps
// holding a lane with n > 16.
// ---------------------------------------------------------------------------
__global__ void __launch_bounds__(512)
check_node_update(const float* __restrict__ x, float* __restrict__ out) {
    __shared__ float s_x[IN_DIM + 4];   // +sentinel, padded

    const int tid = threadIdx.x;                 // 0..511
    const int b   = blockIdx.y;                  // 0..127
    const int o   = blockIdx.x * 512 + tid;      // consecutive across warp

    // One memory epoch: stage load + count + 16 index loads, all independent.
    const float4 stage =
        reinterpret_cast<const float4*>(x + (size_t)b * IN_DIM)[tid];
    const int n = g_cnt[o];
    unsigned short id[NSTRAIGHT];
    #pragma unroll
    for (int k = 0; k < NSTRAIGHT; k++)
        id[k] = g_idxT[k][o];                    // 64B coalesced per warp

    reinterpret_cast<float4*>(s_x)[tid] = stage;
    if (tid == 0) s_x[IN_DIM] = 1.0f;            // sentinel
    __syncthreads();

    float v[NSTRAIGHT];
    #pragma unroll
    for (int k = 0; k < NSTRAIGHT; k++)
        v[k] = s_x[id[k]];                       // unconditional LDS gathers

    float p = (((v[0]  * v[1])  * (v[2]  * v[3])) *
               ((v[4]  * v[5])  * (v[6]  * v[7]))) *
              (((v[8]  * v[9])  * (v[10] * v[11])) *
               ((v[12] * v[13]) * (v[14] * v[15])));

    #pragma unroll 1
    for (int j = NSTRAIGHT; j < n; j++)          // rare (P ~ 0.18% per lane)
        p *= s_x[g_idxT[j][o]];

    const float lim = 1.0f - 1e-7f;              // folds to 0.99999988f
    p = fminf(fmaxf(p, -lim), lim);

    out[(size_t)b * OUT_DIM + o] = __logf((1.0f + p) / (1.0f - p));
}

// ---------------------------------------------------------------------------
extern "C" void kernel_launch(void* const* d_in, const int* in_sizes, int n_in,
                              void* d_out, int out_size) {
    const float* x    = (const float*)d_in[0];   // [128, 2048]
    const float* mask = (const float*)d_in[1];   // [1024, 2048]
    float*       out  = (float*)d_out;           // [128, 1024]

    // 1024 rows, one warp each: 256 blocks x 4 warps -> covers all 148 SMs
    build_row_indices<<<256, 128>>>(mask);

    dim3 grd(OUT_DIM / 512, BATCH);              // (2, 128) = 256 blocks
    check_node_update<<<grd, 512>>>(x, out);
}

// round 4
// speedup vs baseline: 1.0358x; 1.0358x over previous
#include <cuda_runtime.h>
#include <cuda_bf16.h>
#include <math.h>

#define BATCH   128
#define OUT_DIM 1024
#define IN_DIM  2048
#define MAXNNZ  64          // Poisson(8): P(row nnz > 64) ~ 1e-40 — safe cap
#define NSTRAIGHT 16        // unconditional gathers; pad with sentinel IN_DIM

// Scratch (no allocations allowed anywhere):
__device__ int            g_cnt[OUT_DIM];
__device__ unsigned short g_idx[OUT_DIM][MAXNNZ];     // row-major, 128B rows
__device__ float          g_xT[(IN_DIM + 1) * BATCH]; // x transposed + sentinel row of 1.0f

// ---------------------------------------------------------------------------
// Kernel 1 (fused by blockIdx):
//   blocks [0,128):   index build — 8 warps/block, one warp per mask row.
//   blocks [128,192): x transpose — one 32-column strip each, tile transpose.
// ---------------------------------------------------------------------------
__global__ void __launch_bounds__(256)
build_and_transpose(const float* __restrict__ mask, const float* __restrict__ x) {
    const int tid  = threadIdx.x;
    const int lane = tid & 31;

    if (blockIdx.x < 128) {
        // ---- index build: warp = mask row ----
        const int o = blockIdx.x * 8 + (tid >> 5);
        const float4* row4 = reinterpret_cast<const float4*>(mask + (size_t)o * IN_DIM);

        float4 v[16];                        // whole 8KB row in flight
        #pragma unroll
        for (int u = 0; u < 16; u++)
            v[u] = row4[u * 32 + lane];

        int mycnt = 0;
        #pragma unroll
        for (int u = 0; u < 16; u++)
            mycnt += (v[u].x != 0.0f) + (v[u].y != 0.0f) +
                     (v[u].z != 0.0f) + (v[u].w != 0.0f);

        int scan = mycnt;                    // inclusive warp scan
        #pragma unroll
        for (int d = 1; d < 32; d <<= 1) {
            int t = __shfl_up_sync(0xffffffffu, scan, d);
            if (lane >= d) scan += t;
        }
        int total = __shfl_sync(0xffffffffu, scan, 31);
        int pos   = scan - mycnt;            // exclusive prefix (order-free OK)

        #pragma unroll
        for (int u = 0; u < 16; u++) {
            float m[4] = {v[u].x, v[u].y, v[u].z, v[u].w};
            #pragma unroll
            for (int k = 0; k < 4; k++) {
                if (m[k] != 0.0f) {
                    if (pos < MAXNNZ)
                        g_idx[o][pos] = (unsigned short)((u * 32 + lane) * 4 + k);
                    pos++;
                }
            }
        }
        for (int j = total + lane; j < NSTRAIGHT; j += 32)   // sentinel pad
            g_idx[o][j] = (unsigned short)IN_DIM;
        if (lane == 0) g_cnt[o] = total < MAXNNZ ? total : MAXNNZ;

    } else {
        // ---- transpose strip: 32 columns x 128 batches ----
        __shared__ float tile[32][33];
        const int c0 = (blockIdx.x - 128) * 32;
        const int tx = tid & 31;
        const int ty = tid >> 5;             // 0..7

        #pragma unroll
        for (int bt = 0; bt < 4; bt++) {
            const int b0 = bt * 32;
            #pragma unroll
            for (int i = 0; i < 4; i++)
                tile[ty + 8 * i][tx] =
                    x[(size_t)(b0 + ty + 8 * i) * IN_DIM + c0 + tx];
            __syncthreads();
            #pragma unroll
            for (int i = 0; i < 4; i++)
                g_xT[(size_t)(c0 + ty + 8 * i) * BATCH + b0 + tx] =
                    tile[tx][ty + 8 * i];
            __syncthreads();
        }
        if (blockIdx.x == 128 && tid < BATCH)        // sentinel row -> 1.0f
            g_xT[(size_t)IN_DIM * BATCH + tid] = 1.0f;
    }
}

// ---------------------------------------------------------------------------
// Kernel 2: block = 32 check nodes x 32 batches (1024 threads).
// Warp w owns o = o0+w for ALL 32 lanes -> index list + n are warp-uniform
// (broadcast loads, no divergence). Message loads xT[idx][b0+lane] are fully
// coalesced 128B. Output transposed through shared for coalesced stores.
// ---------------------------------------------------------------------------
__global__ void __launch_bounds__(1024)
check_node_update(float* __restrict__ out) {
    __shared__ float s_t[32][33];

    const int tx = threadIdx.x & 31;            // batch lane
    const int w  = threadIdx.x >> 5;            // check node within tile
    const int o  = blockIdx.x * 32 + w;
    const int b0 = blockIdx.y * 32;

    // 16 padded indices: two uniform 16B loads (broadcast across the warp)
    const uint4* gi = reinterpret_cast<const uint4*>(&g_idx[o][0]);
    const uint4 A = gi[0], B = gi[1];
    const int   n = g_cnt[o];

    int id[NSTRAIGHT];
    {
        const unsigned wds[8] = {A.x, A.y, A.z, A.w, B.x, B.y, B.z, B.w};
        #pragma unroll
        for (int k = 0; k < 8; k++) {
            id[2 * k]     = wds[k] & 0xffffu;
            id[2 * k + 1] = wds[k] >> 16;
        }
    }

    // 16 independent, fully coalesced gathers (sentinel rows give 1.0f)
    float v[NSTRAIGHT];
    #pragma unroll
    for (int k = 0; k < NSTRAIGHT; k++)
        v[k] = g_xT[(size_t)id[k] * BATCH + b0 + tx];

    float p = (((v[0]  * v[1])  * (v[2]  * v[3])) *
               ((v[4]  * v[5])  * (v[6]  * v[7]))) *
              (((v[8]  * v[9])  * (v[10] * v[11])) *
               ((v[12] * v[13]) * (v[14] * v[15])));

    #pragma unroll 1
    for (int j = NSTRAIGHT; j < n; j++)          // warp-uniform, ~2/1024 rows
        p *= g_xT[(size_t)g_idx[o][j] * BATCH + b0 + tx];

    const float lim = 1.0f - 1e-7f;              // folds to 0.99999988f
    p = fminf(fmaxf(p, -lim), lim);

    s_t[w][tx] = __logf((1.0f + p) / (1.0f - p));
    __syncthreads();

    // thread (w,tx) -> out[b0+w][o0+tx], coalesced 128B per warp
    out[(size_t)(b0 + w) * OUT_DIM + blockIdx.x * 32 + tx] = s_t[tx][w];
}

// ---------------------------------------------------------------------------
extern "C" void kernel_launch(void* const* d_in, const int* in_sizes, int n_in,
                              void* d_out, int out_size) {
    const float* x    = (const float*)d_in[0];   // [128, 2048]
    const float* mask = (const float*)d_in[1];   // [1024, 2048]
    float*       out  = (float*)d_out;           // [128, 1024]

    build_and_transpose<<<192, 256>>>(mask, x);  // 128 build + 64 transpose

    dim3 grd(OUT_DIM / 32, BATCH / 32);          // (32, 4) = 128 blocks
    check_node_update<<<grd, 1024>>>(out);
}